// round 16
// baseline (speedup 1.0000x reference)
#include <cuda_runtime.h>
#include <cuda_bf16.h>
#include <math.h>

// Problem constants
#define BB 2
#define TT 512
#define HH 128
#define EE 32
#define VV 32000
#define NN (BB*TT)          // 1024

#define LOGITS_ELEMS ((long long)BB*TT*VV)   // 32768000
#define HID_OFF LOGITS_ELEMS
#define W_OFF   (LOGITS_ELEMS + (long long)BB*HH)  // 32768256

// -------------------- scratch (device globals; no allocation allowed) ------
__device__ float g_xp   [NN*HH];
__device__ float g_rnn  [NN*HH];
__device__ float g_q    [NN*HH];
__device__ float g_kT   [HH*NN];       // transposed: kT[h][n]
__device__ float g_ctx  [NN*HH];
__device__ float g_out2T[HH*NN];       // transposed: out2T[k][n]
__device__ float g_W1T  [HH*HH];
__device__ float g_W2T  [HH*HH];
__device__ float g_WpT  [2*HH*HH];
__device__ float g_WfcT [HH*VV];       // 16.4 MB
__device__ int   g_is64;

// -------------------- packed f32x2 helpers ---------------------------------
__device__ __forceinline__ unsigned long long pack2(float lo, float hi) {
    unsigned long long r;
    asm("mov.b64 %0, {%1,%2};" : "=l"(r) : "f"(lo), "f"(hi));
    return r;
}
__device__ __forceinline__ unsigned long long fma2(unsigned long long a,
                                                   unsigned long long b,
                                                   unsigned long long c) {
    unsigned long long d;
    asm("fma.rn.f32x2 %0, %1, %2, %3;" : "=l"(d) : "l"(a), "l"(b), "l"(c));
    return d;
}
__device__ __forceinline__ unsigned long long add2(unsigned long long a,
                                                   unsigned long long b) {
    unsigned long long d;
    asm("add.rn.f32x2 %0, %1, %2;" : "=l"(d) : "l"(a), "l"(b));
    return d;
}
__device__ __forceinline__ float2 unpack2(unsigned long long v) {
    float2 f;
    asm("mov.b64 {%0,%1}, %2;" : "=f"(f.x), "=f"(f.y) : "l"(v));
    return f;
}

// Fast, near-exact tanh: tanh(x) = 1 - 2/(exp(2x)+1).  (EX2+RCP MUFU path;
// abs err ~2e-7 — well inside the 1e-3 budget, ~3x cheaper than tanhf.)
__device__ __forceinline__ float ftanh(float x) {
    float e = __expf(fminf(fmaxf(2.f * x, -30.f), 30.f));
    return 1.f - __fdividef(2.f, e + 1.f);
}

// -------------------- transpose tile body -----------------------------------
__device__ __forceinline__ void tr_tile(const float* __restrict__ src,
                                        float* __restrict__ dst,
                                        int M, int N, int bx, int by,
                                        float (*tile)[33]) {
    int x = threadIdx.x, y = threadIdx.y;   // 32 x 8
    int b0x = bx * 32, b0y = by * 32;
#pragma unroll
    for (int dy = 0; dy < 32; dy += 8) {
        int m = b0y + y + dy, n = b0x + x;
        if (m < M && n < N) tile[y + dy][x] = src[(long long)m * N + n];
    }
    __syncthreads();
#pragma unroll
    for (int dy = 0; dy < 32; dy += 8) {
        int n = b0x + y + dy, m = b0y + x;
        if (n < N && m < M) dst[(long long)n * M + m] = tile[x][y + dy];
    }
}

// -------------------- K0: fused detect + small transposes ------------------
// block 0: int64/int32 detection of x; blocks 1..16 W1^T; 17..32 W2^T;
// 33..64 Wp^T.
__global__ void k_misc(const int* __restrict__ x32,
                       const float* __restrict__ W1,
                       const float* __restrict__ W2,
                       const float* __restrict__ Wp) {
    __shared__ float tile[32][33];
    int b = blockIdx.x;
    if (b == 0) {
        if (threadIdx.y == 0) {
            int tid = threadIdx.x;
            int bad = 0;
            for (int j = tid; j < 512; j += 32)
                if (x32[2*j + 1] != 0) bad = 1;
            unsigned m = __ballot_sync(0xffffffffu, bad);
            if (tid == 0) g_is64 = (m == 0) ? 1 : 0;
        }
        return;
    }
    if (b <= 16) {
        int i = b - 1;  tr_tile(W1, g_W1T, HH, HH, i & 3, i >> 2, tile);
    } else if (b <= 32) {
        int i = b - 17; tr_tile(W2, g_W2T, HH, HH, i & 3, i >> 2, tile);
    } else {
        int i = b - 33; tr_tile(Wp, g_WpT, HH, 2*HH, i & 7, i >> 3, tile);
    }
}

// -------------------- Ktr: tiled transpose for Wfc ---------------------------
__global__ void k_transpose(const float* __restrict__ src,
                            float* __restrict__ dst, int M, int N) {
    __shared__ float tile[32][33];
    tr_tile(src, dst, M, N, blockIdx.x, blockIdx.y, tile);
}

// -------------------- K1: embedding gather + input projection --------------
__global__ void k_embed(const void* __restrict__ x,
                        const float* __restrict__ emb_t,
                        const float* __restrict__ W_ih,
                        const float* __restrict__ b_ih,
                        const float* __restrict__ b_hh) {
    int n = blockIdx.x;
    int i = threadIdx.x;
    __shared__ __align__(16) float e_sh[EE];
    if (i < EE) {
        long long idx = g_is64 ? ((const long long*)x)[n]
                               : (long long)((const int*)x)[n];
        e_sh[i] = emb_t[idx * EE + i];
    }
    __syncthreads();
    float acc = b_ih[i] + b_hh[i];
    const float4* w = (const float4*)(W_ih + i * EE);
#pragma unroll
    for (int u = 0; u < EE/4; u++) {
        float4 wv = w[u];
        acc += wv.x * e_sh[4*u+0] + wv.y * e_sh[4*u+1]
             + wv.z * e_sh[4*u+2] + wv.w * e_sh[4*u+3];
    }
    g_xp[n * HH + i] = acc;
}

// -------------------- K2: sequential RNN scan --------------------------------
// grid(2) x block(512): 128 outputs x 4 lanes. Bank-conflict-free h reads via
// per-q chunk rotation (u' = (u+2q)&7): distinct banks across the 4 q-slices.
__global__ void k_rnn(const float* __restrict__ W_hh,
                      const float* __restrict__ hidden,
                      float* __restrict__ hid_out) {
    int b   = blockIdx.x;
    int tid = threadIdx.x;
    int i   = tid >> 2;       // output index 0..127
    int q   = tid & 3;        // lane within output (32 MACs each)
    int rot = 2 * q;

    __shared__ __align__(16) float h_sh[2][HH];

    // weights in rotated chunk order so fma pairing matches rotated h reads
    const ulonglong2* wrow =
        reinterpret_cast<const ulonglong2*>(W_hh + i*HH + q*32);
    ulonglong2 wv[8];
#pragma unroll
    for (int u = 0; u < 8; u++) wv[u] = wrow[(u + rot) & 7];

    if (q == 0) h_sh[0][i] = hidden[b*HH + i];
    __syncthreads();

    float xpv = g_xp[(b*TT + 0)*HH + i];
    int buf = 0;
    for (int t = 0; t < TT; t++) {
        float xnext = (t < TT-1) ? g_xp[(b*TT + t + 1)*HH + i] : 0.f;

        const ulonglong2* hp =
            reinterpret_cast<const ulonglong2*>(&h_sh[buf][q*32]);
        unsigned long long a0 = 0ull, a1 = 0ull, a2 = 0ull, a3 = 0ull;
#pragma unroll
        for (int u = 0; u < 8; u += 2) {
            ulonglong2 h0 = hp[(u + 0 + rot) & 7];
            ulonglong2 h1 = hp[(u + 1 + rot) & 7];
            a0 = fma2(wv[u].x,   h0.x, a0);
            a1 = fma2(wv[u].y,   h0.y, a1);
            a2 = fma2(wv[u+1].x, h1.x, a2);
            a3 = fma2(wv[u+1].y, h1.y, a3);
        }
        a0 = add2(a0, a2);
        a1 = add2(a1, a3);
        a0 = add2(a0, a1);
        float2 f = unpack2(a0);
        float p = f.x + f.y;
        p += __shfl_xor_sync(0xffffffffu, p, 1);
        p += __shfl_xor_sync(0xffffffffu, p, 2);

        if (q == 0) {
            float hn = ftanh(xpv + p);
            h_sh[buf ^ 1][i] = hn;
            g_rnn[(b*TT + t)*HH + i] = hn;
        }
        xpv = xnext;
        buf ^= 1;
        __syncthreads();
    }
    if (q == 0) hid_out[b*HH + i] = h_sh[buf][i];
}

// -------------------- K3: q/k projections (transposed weights) -------------
#define QK_R 8
__global__ void k_qk(const float* __restrict__ W1T,
                     const float* __restrict__ W2T) {
    int n0  = blockIdx.x * QK_R;
    int tid = threadIdx.x;                       // 256
    __shared__ __align__(16) float rT[HH * 12];  // rT[j*12 + r]

    for (int idx = tid; idx < QK_R * HH; idx += 256) {
        int j = idx & 127, r = idx >> 7;
        rT[j*12 + r] = g_rnn[(n0 + r)*HH + j];
    }
    __syncthreads();

    int i     = tid & 127;
    int which = tid >> 7;
    const float* WT = which ? W2T : W1T;

    float acc[QK_R];
#pragma unroll
    for (int r = 0; r < QK_R; r++) acc[r] = 0.f;

#pragma unroll 4
    for (int j = 0; j < HH; j++) {
        float wv = WT[j*HH + i];
        float4 r0 = *(const float4*)&rT[j*12];
        float4 r1 = *(const float4*)&rT[j*12 + 4];
        acc[0] += wv*r0.x; acc[1] += wv*r0.y;
        acc[2] += wv*r0.z; acc[3] += wv*r0.w;
        acc[4] += wv*r1.x; acc[5] += wv*r1.y;
        acc[6] += wv*r1.z; acc[7] += wv*r1.w;
    }
    if (which == 0) {
#pragma unroll
        for (int r = 0; r < QK_R; r++) g_q[(n0 + r)*HH + i] = acc[r];
    } else {
#pragma unroll
        for (int r = 0; r < QK_R; r++) g_kT[i*NN + n0 + r] = acc[r];
    }
}

// -------------------- K4: attention row (scores + softmax + context) --------
__global__ void k_attn(const float* __restrict__ vvec,
                       float* __restrict__ wout) {
    int t = blockIdx.x, b = blockIdx.y;
    int tid = threadIdx.x, lane = tid & 31, w = tid >> 5;

    __shared__ __align__(16) float qrow[HH], vsh[HH];
    __shared__ float sc[TT];
    __shared__ float red[8];
    __shared__ float stat;
    __shared__ float cpart[2][HH];

    if (tid < HH) {
        qrow[tid] = g_q[(b*TT + t)*HH + tid];
        vsh[tid]  = vvec[tid];
    }
    __syncthreads();

    // scores: thread s computes full dot over h (coalesced via g_kT)
    for (int s = tid; s <= t; s += 256) {
        const float* kc = g_kT + b*TT + s;
        float a0 = 0.f, a1 = 0.f, a2 = 0.f, a3 = 0.f;
#pragma unroll 4
        for (int h = 0; h < HH; h += 4) {
            float4 qq = *(const float4*)&qrow[h];
            float4 vv = *(const float4*)&vsh[h];
            a0 += ftanh(qq.x + kc[(h+0)*NN]) * vv.x;
            a1 += ftanh(qq.y + kc[(h+1)*NN]) * vv.y;
            a2 += ftanh(qq.z + kc[(h+2)*NN]) * vv.z;
            a3 += ftanh(qq.w + kc[(h+3)*NN]) * vv.w;
        }
        sc[s] = (a0 + a1) + (a2 + a3);
    }
    __syncthreads();

    // softmax over sc[0..t]
    float m = -1e30f;
    for (int s = tid; s <= t; s += 256) m = fmaxf(m, sc[s]);
#pragma unroll
    for (int o = 16; o > 0; o >>= 1)
        m = fmaxf(m, __shfl_xor_sync(0xffffffffu, m, o));
    if (lane == 0) red[w] = m;
    __syncthreads();
    if (tid == 0) {
        float mm = red[0];
        for (int j = 1; j < 8; j++) mm = fmaxf(mm, red[j]);
        stat = mm;
    }
    __syncthreads();
    float mx = stat;

    float sum = 0.f;
    for (int s = tid; s <= t; s += 256) {
        float e = __expf(sc[s] - mx);
        sc[s] = e;
        sum += e;
    }
#pragma unroll
    for (int o = 16; o > 0; o >>= 1)
        sum += __shfl_xor_sync(0xffffffffu, sum, o);
    if (lane == 0) red[w] = sum;
    __syncthreads();
    if (tid == 0) {
        float ss = 0.f;
        for (int j = 0; j < 8; j++) ss += red[j];
        stat = ss;
    }
    __syncthreads();
    float inv = 1.f / stat;

    for (int s = tid; s < TT; s += 256) {
        float wt = (s <= t) ? sc[s] * inv : 0.f;
        wout[((long long)(b*TT + t))*TT + s] = wt;
        if (s <= t) sc[s] = wt;
    }
    __syncthreads();

    // context[b,t,h] = sum_s w[s]*rnn[b,s,h]
    int half = tid >> 7, h = tid & (HH - 1);
    float acc = 0.f;
    for (int s = half; s <= t; s += 2)
        acc += sc[s] * g_rnn[(b*TT + s)*HH + h];
    cpart[half][h] = acc;
    __syncthreads();
    if (tid < HH)
        g_ctx[(b*TT + t)*HH + tid] = cpart[0][tid] + cpart[1][tid];
}

// -------------------- K5: combined projection + relu (transposed Wp) -------
__global__ void k_proj(const float* __restrict__ WpT,
                       const float* __restrict__ bp) {
    int n0  = blockIdx.x * QK_R;
    int tid = threadIdx.x;                            // 128
    __shared__ __align__(16) float cT[2*HH * 12];     // cT[j*12 + r]

    for (int idx = tid; idx < QK_R * 2*HH; idx += 128) {
        int j = idx & 255, r = idx >> 8;
        float v = (j < HH) ? g_rnn[(n0 + r)*HH + j]
                           : g_ctx[(n0 + r)*HH + (j - HH)];
        cT[j*12 + r] = v;
    }
    __syncthreads();

    int i = tid;
    float bias = bp[i];
    float acc[QK_R];
#pragma unroll
    for (int r = 0; r < QK_R; r++) acc[r] = bias;

#pragma unroll 4
    for (int j = 0; j < 2*HH; j++) {
        float wv = WpT[j*HH + i];
        float4 r0 = *(const float4*)&cT[j*12];
        float4 r1 = *(const float4*)&cT[j*12 + 4];
        acc[0] += wv*r0.x; acc[1] += wv*r0.y;
        acc[2] += wv*r0.z; acc[3] += wv*r0.w;
        acc[4] += wv*r1.x; acc[5] += wv*r1.y;
        acc[6] += wv*r1.z; acc[7] += wv*r1.w;
    }
#pragma unroll
    for (int r = 0; r < QK_R; r++)
        g_out2T[i*NN + n0 + r] = fmaxf(acc[r], 0.f);
}

// -------------------- K6: final FC  logits = out2 @ Wfc^T + bfc -------------
// 128x128 block tile; K split into 2 chunks of 64 -> 64KB smem -> 2 blocks/SM
// so the gmem load tail of one block overlaps compute of the other.
#define FCD 128
#define FCK 64
#define FC_SMEM (2*FCK*FCD*4)    // 65536 bytes

__global__ void __launch_bounds__(256, 2)
k_fc(const float* __restrict__ WfcT,
     const float* __restrict__ bfc,
     float* __restrict__ logits) {
    extern __shared__ float sm[];
    float* As = sm;              // As[k][r]  (k-major), k in chunk
    float* Bs = sm + FCK*FCD;    // Bs[k][c]

    int tid = threadIdx.x;
    int cb = blockIdx.x * FCD;
    int rb = blockIdx.y * FCD;

    int w = tid >> 5, l = tid & 31;
    int rBase = (w & 3)*32 + (l >> 3)*8;
    int cBase = (w >> 2)*64 + (l & 7)*8;

    unsigned long long acc[8][4];
#pragma unroll
    for (int r = 0; r < 8; r++)
#pragma unroll
        for (int c = 0; c < 4; c++) acc[r][c] = 0ull;

    int k0 = tid >> 5;           // 0..7
    int q4 = tid & 31;           // float4 index within row

#pragma unroll
    for (int kc = 0; kc < HH/FCK; kc++) {
#pragma unroll
        for (int p = 0; p < FCK/8; p++) {
            int kk = k0 + p*8;
            *(float4*)&As[kk*FCD + q4*4] =
                *(const float4*)(g_out2T + (kc*FCK + kk)*NN + rb + q4*4);
            *(float4*)&Bs[kk*FCD + q4*4] =
                *(const float4*)(WfcT + (long long)(kc*FCK + kk)*VV + cb + q4*4);
        }
        __syncthreads();

#pragma unroll 4
        for (int kk = 0; kk < FCK; kk++) {
            float4 a0 = *(const float4*)&As[kk*FCD + rBase];
            float4 a1 = *(const float4*)&As[kk*FCD + rBase + 4];
            ulonglong2 b0 = *(const ulonglong2*)&Bs[kk*FCD + cBase];
            ulonglong2 b1 = *(const ulonglong2*)&Bs[kk*FCD + cBase + 4];
            float av[8] = {a0.x, a0.y, a0.z, a0.w, a1.x, a1.y, a1.z, a1.w};
#pragma unroll
            for (int r = 0; r < 8; r++) {
                unsigned long long ar = pack2(av[r], av[r]);
                acc[r][0] = fma2(ar, b0.x, acc[r][0]);
                acc[r][1] = fma2(ar, b0.y, acc[r][1]);
                acc[r][2] = fma2(ar, b1.x, acc[r][2]);
                acc[r][3] = fma2(ar, b1.y, acc[r][3]);
            }
        }
        __syncthreads();
    }

    float4 bf0 = *(const float4*)(bfc + cb + cBase);
    float4 bf1 = *(const float4*)(bfc + cb + cBase + 4);
#pragma unroll
    for (int r = 0; r < 8; r++) {
        float2 p0 = unpack2(acc[r][0]);
        float2 p1 = unpack2(acc[r][1]);
        float2 p2 = unpack2(acc[r][2]);
        float2 p3 = unpack2(acc[r][3]);
        float4 o0 = make_float4(p0.x + bf0.x, p0.y + bf0.y,
                                p1.x + bf0.z, p1.y + bf0.w);
        float4 o1 = make_float4(p2.x + bf1.x, p2.y + bf1.y,
                                p3.x + bf1.z, p3.y + bf1.w);
        float* dst = logits + (long long)(rb + rBase + r)*VV + cb + cBase;
        *(float4*)(dst)     = o0;
        *(float4*)(dst + 4) = o1;
    }
}

// -------------------- launcher ----------------------------------------------
extern "C" void kernel_launch(void* const* d_in, const int* in_sizes, int n_in,
                              void* d_out, int out_size) {
    const void*  x      = d_in[0];
    const float* hidden = (const float*)d_in[1];
    const float* emb    = (const float*)d_in[2];
    const float* W_ih   = (const float*)d_in[3];
    const float* W_hh   = (const float*)d_in[4];
    const float* b_ih   = (const float*)d_in[5];
    const float* b_hh   = (const float*)d_in[6];
    const float* W1     = (const float*)d_in[7];
    const float* W2     = (const float*)d_in[8];
    const float* v      = (const float*)d_in[9];
    const float* Wp     = (const float*)d_in[10];
    const float* bp     = (const float*)d_in[11];
    const float* Wfc    = (const float*)d_in[12];
    const float* bfc    = (const float*)d_in[13];

    float* out     = (float*)d_out;
    float* logits  = out;
    float* hid_out = out + HID_OFF;
    float* w_out   = out + W_OFF;

    float *dW1T, *dW2T, *dWpT, *dWfcT;
    cudaGetSymbolAddress((void**)&dW1T,  g_W1T);
    cudaGetSymbolAddress((void**)&dW2T,  g_W2T);
    cudaGetSymbolAddress((void**)&dWpT,  g_WpT);
    cudaGetSymbolAddress((void**)&dWfcT, g_WfcT);

    cudaFuncSetAttribute(k_fc, cudaFuncAttributeMaxDynamicSharedMemorySize,
                         FC_SMEM);

    dim3 tb(32, 8);
    // launch order chosen so the profiler's fixed capture slot (4th launch)
    // lands on k_rnn — the kernel whose cost model is least certain.
    k_misc     <<<65, tb>>>((const int*)x, W1, W2, Wp);          // 1
    k_embed    <<<NN, HH>>>(x, emb, W_ih, b_ih, b_hh);           // 2
    k_transpose<<<dim3(4, 1000), tb>>>(Wfc, dWfcT, VV, HH);      // 3
    k_rnn      <<<BB, 512>>>(W_hh, hidden, hid_out);             // 4 <- ncu
    k_qk       <<<NN/QK_R, 256>>>(dW1T, dW2T);                   // 5
    k_attn     <<<dim3(TT, BB), 256>>>(v, w_out);                // 6
    k_proj     <<<NN/QK_R, 128>>>(dWpT, bp);                     // 7
    k_fc       <<<dim3(VV/FCD, NN/FCD), 256, FC_SMEM>>>(dWfcT, bfc, logits); // 8
}

// round 17
// speedup vs baseline: 1.1454x; 1.1454x over previous
#include <cuda_runtime.h>
#include <cuda_bf16.h>
#include <math.h>

// Problem constants
#define BB 2
#define TT 512
#define HH 128
#define EE 32
#define VV 32000
#define NN (BB*TT)          // 1024

#define LOGITS_ELEMS ((long long)BB*TT*VV)   // 32768000
#define HID_OFF LOGITS_ELEMS
#define W_OFF   (LOGITS_ELEMS + (long long)BB*HH)  // 32768256

// -------------------- scratch (device globals; no allocation allowed) ------
__device__ float g_xp   [NN*HH];
__device__ float g_rnn  [NN*HH];
__device__ float g_q    [NN*HH];
__device__ float g_kT   [HH*NN];       // transposed: kT[h][n]
__device__ float g_ctx  [NN*HH];
__device__ float g_out2T[HH*NN];       // transposed: out2T[k][n]
__device__ float g_W1T  [HH*HH];
__device__ float g_W2T  [HH*HH];
__device__ float g_WpT  [2*HH*HH];
__device__ float g_WfcT [HH*VV];       // 16.4 MB
__device__ int   g_is64;

// -------------------- packed f32x2 helpers ---------------------------------
__device__ __forceinline__ unsigned long long pack2(float lo, float hi) {
    unsigned long long r;
    asm("mov.b64 %0, {%1,%2};" : "=l"(r) : "f"(lo), "f"(hi));
    return r;
}
__device__ __forceinline__ unsigned long long fma2(unsigned long long a,
                                                   unsigned long long b,
                                                   unsigned long long c) {
    unsigned long long d;
    asm("fma.rn.f32x2 %0, %1, %2, %3;" : "=l"(d) : "l"(a), "l"(b), "l"(c));
    return d;
}
__device__ __forceinline__ unsigned long long add2(unsigned long long a,
                                                   unsigned long long b) {
    unsigned long long d;
    asm("add.rn.f32x2 %0, %1, %2;" : "=l"(d) : "l"(a), "l"(b));
    return d;
}
__device__ __forceinline__ float2 unpack2(unsigned long long v) {
    float2 f;
    asm("mov.b64 {%0,%1}, %2;" : "=f"(f.x), "=f"(f.y) : "l"(v));
    return f;
}

// Fast, near-exact tanh: tanh(x) = 1 - 2/(exp(2x)+1).
// No clamps needed: __expf saturates to inf/0 and the identity still yields
// exactly +/-1 at the extremes. abs err ~2e-7.
__device__ __forceinline__ float ftanh(float x) {
    float e = __expf(2.f * x);
    return 1.f - __fdividef(2.f, e + 1.f);
}

// -------------------- transpose tile body -----------------------------------
__device__ __forceinline__ void tr_tile(const float* __restrict__ src,
                                        float* __restrict__ dst,
                                        int M, int N, int bx, int by,
                                        float (*tile)[33]) {
    int x = threadIdx.x, y = threadIdx.y;   // 32 x 8
    int b0x = bx * 32, b0y = by * 32;
#pragma unroll
    for (int dy = 0; dy < 32; dy += 8) {
        int m = b0y + y + dy, n = b0x + x;
        if (m < M && n < N) tile[y + dy][x] = src[(long long)m * N + n];
    }
    __syncthreads();
#pragma unroll
    for (int dy = 0; dy < 32; dy += 8) {
        int n = b0x + y + dy, m = b0y + x;
        if (n < N && m < M) dst[(long long)n * M + m] = tile[x][y + dy];
    }
}

// -------------------- K0: fused detect + small transposes ------------------
__global__ void k_misc(const int* __restrict__ x32,
                       const float* __restrict__ W1,
                       const float* __restrict__ W2,
                       const float* __restrict__ Wp) {
    __shared__ float tile[32][33];
    int b = blockIdx.x;
    if (b == 0) {
        if (threadIdx.y == 0) {
            int tid = threadIdx.x;
            int bad = 0;
            for (int j = tid; j < 512; j += 32)
                if (x32[2*j + 1] != 0) bad = 1;
            unsigned m = __ballot_sync(0xffffffffu, bad);
            if (tid == 0) g_is64 = (m == 0) ? 1 : 0;
        }
        return;
    }
    if (b <= 16) {
        int i = b - 1;  tr_tile(W1, g_W1T, HH, HH, i & 3, i >> 2, tile);
    } else if (b <= 32) {
        int i = b - 17; tr_tile(W2, g_W2T, HH, HH, i & 3, i >> 2, tile);
    } else {
        int i = b - 33; tr_tile(Wp, g_WpT, HH, 2*HH, i & 7, i >> 3, tile);
    }
}

// -------------------- Ktr: tiled transpose for Wfc ---------------------------
__global__ void k_transpose(const float* __restrict__ src,
                            float* __restrict__ dst, int M, int N) {
    __shared__ float tile[32][33];
    tr_tile(src, dst, M, N, blockIdx.x, blockIdx.y, tile);
}

// -------------------- K1: embedding gather + input projection --------------
__global__ void k_embed(const void* __restrict__ x,
                        const float* __restrict__ emb_t,
                        const float* __restrict__ W_ih,
                        const float* __restrict__ b_ih,
                        const float* __restrict__ b_hh) {
    int n = blockIdx.x;
    int i = threadIdx.x;
    __shared__ __align__(16) float e_sh[EE];
    if (i < EE) {
        long long idx = g_is64 ? ((const long long*)x)[n]
                               : (long long)((const int*)x)[n];
        e_sh[i] = emb_t[idx * EE + i];
    }
    __syncthreads();
    float acc = b_ih[i] + b_hh[i];
    const float4* w = (const float4*)(W_ih + i * EE);
#pragma unroll
    for (int u = 0; u < EE/4; u++) {
        float4 wv = w[u];
        acc += wv.x * e_sh[4*u+0] + wv.y * e_sh[4*u+1]
             + wv.z * e_sh[4*u+2] + wv.w * e_sh[4*u+3];
    }
    g_xp[n * HH + i] = acc;
}

// -------------------- K2: sequential RNN scan (latency-optimized) ----------
// grid(2) x block(256): 128 outputs x 2 lanes (64 MACs each).
// Critical-path fixes vs prior version:
//   * 4-deep register ring for xp: LDG issued 3 steps ahead of use.
//   * single shuffle reduce (q pairs, shfl_xor 1).
//   * 8 warps -> cheaper per-step __syncthreads.
//   * chunk rotation (4*q over 16 chunks) keeps the two q-groups on
//     disjoint smem banks.
__global__ void k_rnn(const float* __restrict__ W_hh,
                      const float* __restrict__ hidden,
                      float* __restrict__ hid_out) {
    int b   = blockIdx.x;
    int tid = threadIdx.x;
    int i   = tid >> 1;       // output index 0..127
    int q   = tid & 1;        // half of the dot product (64 MACs)
    int rot = 4 * q;          // rotation among the 16 16B-chunks of the half

    __shared__ __align__(16) float h_sh[2][HH];

    // 64 weights as 16 ulonglong2 chunks, stored rotated to match h reads
    const ulonglong2* wrow =
        reinterpret_cast<const ulonglong2*>(W_hh + i*HH + q*64);
    ulonglong2 wv[16];
#pragma unroll
    for (int u = 0; u < 16; u++) wv[u] = wrow[(u + rot) & 15];

    if (q == 0) h_sh[0][i] = hidden[b*HH + i];

    const float* xp_col = g_xp + b*TT*HH + i;
    float xr[4];
#pragma unroll
    for (int j = 0; j < 3; j++) xr[j] = xp_col[j*HH];
    __syncthreads();

    int buf = 0;
    for (int t0 = 0; t0 < TT; t0 += 4) {
#pragma unroll
        for (int dt = 0; dt < 4; dt++) {
            int t = t0 + dt;
            // prefetch 3 steps ahead (static ring index under full unroll)
            if (t + 3 < TT) xr[(dt + 3) & 3] = xp_col[(t + 3)*HH];

            const ulonglong2* hp =
                reinterpret_cast<const ulonglong2*>(&h_sh[buf][q*64]);
            unsigned long long a0 = 0ull, a1 = 0ull, a2 = 0ull, a3 = 0ull;
#pragma unroll
            for (int u = 0; u < 16; u += 2) {
                ulonglong2 h0 = hp[(u + 0 + rot) & 15];
                ulonglong2 h1 = hp[(u + 1 + rot) & 15];
                a0 = fma2(wv[u].x,   h0.x, a0);
                a1 = fma2(wv[u].y,   h0.y, a1);
                a2 = fma2(wv[u+1].x, h1.x, a2);
                a3 = fma2(wv[u+1].y, h1.y, a3);
            }
            a0 = add2(a0, a2);
            a1 = add2(a1, a3);
            a0 = add2(a0, a1);
            float2 f = unpack2(a0);
            float p = f.x + f.y;
            p += __shfl_xor_sync(0xffffffffu, p, 1);

            float hn = ftanh(xr[dt] + p);   // both lanes compute (no branch)
            if (q == 0) {
                h_sh[buf ^ 1][i] = hn;
                g_rnn[(b*TT + t)*HH + i] = hn;
            }
            buf ^= 1;
            __syncthreads();
        }
    }
    if (q == 0) hid_out[b*HH + i] = h_sh[buf][i];
}

// -------------------- K3: q/k projections (transposed weights) -------------
#define QK_R 8
__global__ void k_qk(const float* __restrict__ W1T,
                     const float* __restrict__ W2T) {
    int n0  = blockIdx.x * QK_R;
    int tid = threadIdx.x;                       // 256
    __shared__ __align__(16) float rT[HH * 12];  // rT[j*12 + r]

    for (int idx = tid; idx < QK_R * HH; idx += 256) {
        int j = idx & 127, r = idx >> 7;
        rT[j*12 + r] = g_rnn[(n0 + r)*HH + j];
    }
    __syncthreads();

    int i     = tid & 127;
    int which = tid >> 7;
    const float* WT = which ? W2T : W1T;

    float acc[QK_R];
#pragma unroll
    for (int r = 0; r < QK_R; r++) acc[r] = 0.f;

#pragma unroll 4
    for (int j = 0; j < HH; j++) {
        float wv = WT[j*HH + i];
        float4 r0 = *(const float4*)&rT[j*12];
        float4 r1 = *(const float4*)&rT[j*12 + 4];
        acc[0] += wv*r0.x; acc[1] += wv*r0.y;
        acc[2] += wv*r0.z; acc[3] += wv*r0.w;
        acc[4] += wv*r1.x; acc[5] += wv*r1.y;
        acc[6] += wv*r1.z; acc[7] += wv*r1.w;
    }
    if (which == 0) {
#pragma unroll
        for (int r = 0; r < QK_R; r++) g_q[(n0 + r)*HH + i] = acc[r];
    } else {
#pragma unroll
        for (int r = 0; r < QK_R; r++) g_kT[i*NN + n0 + r] = acc[r];
    }
}

// -------------------- K4: attention row (scores + softmax + context) --------
__global__ void k_attn(const float* __restrict__ vvec,
                       float* __restrict__ wout) {
    int t = blockIdx.x, b = blockIdx.y;
    int tid = threadIdx.x, lane = tid & 31, w = tid >> 5;

    __shared__ __align__(16) float qrow[HH], vsh[HH];
    __shared__ float sc[TT];
    __shared__ float red[8];
    __shared__ float stat;
    __shared__ float cpart[2][HH];

    if (tid < HH) {
        qrow[tid] = g_q[(b*TT + t)*HH + tid];
        vsh[tid]  = vvec[tid];
    }
    __syncthreads();

    // scores: thread s computes full dot over h (coalesced via g_kT)
    for (int s = tid; s <= t; s += 256) {
        const float* kc = g_kT + b*TT + s;
        float a0 = 0.f, a1 = 0.f, a2 = 0.f, a3 = 0.f;
#pragma unroll 4
        for (int h = 0; h < HH; h += 4) {
            float4 qq = *(const float4*)&qrow[h];
            float4 vv = *(const float4*)&vsh[h];
            a0 += ftanh(qq.x + kc[(h+0)*NN]) * vv.x;
            a1 += ftanh(qq.y + kc[(h+1)*NN]) * vv.y;
            a2 += ftanh(qq.z + kc[(h+2)*NN]) * vv.z;
            a3 += ftanh(qq.w + kc[(h+3)*NN]) * vv.w;
        }
        sc[s] = (a0 + a1) + (a2 + a3);
    }
    __syncthreads();

    // softmax over sc[0..t]
    float m = -1e30f;
    for (int s = tid; s <= t; s += 256) m = fmaxf(m, sc[s]);
#pragma unroll
    for (int o = 16; o > 0; o >>= 1)
        m = fmaxf(m, __shfl_xor_sync(0xffffffffu, m, o));
    if (lane == 0) red[w] = m;
    __syncthreads();
    if (tid == 0) {
        float mm = red[0];
        for (int j = 1; j < 8; j++) mm = fmaxf(mm, red[j]);
        stat = mm;
    }
    __syncthreads();
    float mx = stat;

    float sum = 0.f;
    for (int s = tid; s <= t; s += 256) {
        float e = __expf(sc[s] - mx);
        sc[s] = e;
        sum += e;
    }
#pragma unroll
    for (int o = 16; o > 0; o >>= 1)
        sum += __shfl_xor_sync(0xffffffffu, sum, o);
    if (lane == 0) red[w] = sum;
    __syncthreads();
    if (tid == 0) {
        float ss = 0.f;
        for (int j = 0; j < 8; j++) ss += red[j];
        stat = ss;
    }
    __syncthreads();
    float inv = 1.f / stat;

    for (int s = tid; s < TT; s += 256) {
        float wt = (s <= t) ? sc[s] * inv : 0.f;
        wout[((long long)(b*TT + t))*TT + s] = wt;
        if (s <= t) sc[s] = wt;
    }
    __syncthreads();

    // context[b,t,h] = sum_s w[s]*rnn[b,s,h]
    int half = tid >> 7, h = tid & (HH - 1);
    float acc = 0.f;
    for (int s = half; s <= t; s += 2)
        acc += sc[s] * g_rnn[(b*TT + s)*HH + h];
    cpart[half][h] = acc;
    __syncthreads();
    if (tid < HH)
        g_ctx[(b*TT + t)*HH + tid] = cpart[0][tid] + cpart[1][tid];
}

// -------------------- K5: combined projection + relu (transposed Wp) -------
__global__ void k_proj(const float* __restrict__ WpT,
                       const float* __restrict__ bp) {
    int n0  = blockIdx.x * QK_R;
    int tid = threadIdx.x;                            // 128
    __shared__ __align__(16) float cT[2*HH * 12];     // cT[j*12 + r]

    for (int idx = tid; idx < QK_R * 2*HH; idx += 128) {
        int j = idx & 255, r = idx >> 8;
        float v = (j < HH) ? g_rnn[(n0 + r)*HH + j]
                           : g_ctx[(n0 + r)*HH + (j - HH)];
        cT[j*12 + r] = v;
    }
    __syncthreads();

    int i = tid;
    float bias = bp[i];
    float acc[QK_R];
#pragma unroll
    for (int r = 0; r < QK_R; r++) acc[r] = bias;

#pragma unroll 4
    for (int j = 0; j < 2*HH; j++) {
        float wv = WpT[j*HH + i];
        float4 r0 = *(const float4*)&cT[j*12];
        float4 r1 = *(const float4*)&cT[j*12 + 4];
        acc[0] += wv*r0.x; acc[1] += wv*r0.y;
        acc[2] += wv*r0.z; acc[3] += wv*r0.w;
        acc[4] += wv*r1.x; acc[5] += wv*r1.y;
        acc[6] += wv*r1.z; acc[7] += wv*r1.w;
    }
#pragma unroll
    for (int r = 0; r < QK_R; r++)
        g_out2T[i*NN + n0 + r] = fmaxf(acc[r], 0.f);
}

// -------------------- K6: final FC  logits = out2 @ Wfc^T + bfc -------------
#define FCD 128
#define FCK 64
#define FC_SMEM (2*FCK*FCD*4)    // 65536 bytes

__global__ void __launch_bounds__(256, 2)
k_fc(const float* __restrict__ WfcT,
     const float* __restrict__ bfc,
     float* __restrict__ logits) {
    extern __shared__ float sm[];
    float* As = sm;              // As[k][r]  (k-major), k in chunk
    float* Bs = sm + FCK*FCD;    // Bs[k][c]

    int tid = threadIdx.x;
    int cb = blockIdx.x * FCD;
    int rb = blockIdx.y * FCD;

    int w = tid >> 5, l = tid & 31;
    int rBase = (w & 3)*32 + (l >> 3)*8;
    int cBase = (w >> 2)*64 + (l & 7)*8;

    unsigned long long acc[8][4];
#pragma unroll
    for (int r = 0; r < 8; r++)
#pragma unroll
        for (int c = 0; c < 4; c++) acc[r][c] = 0ull;

    int k0 = tid >> 5;           // 0..7
    int q4 = tid & 31;           // float4 index within row

#pragma unroll
    for (int kc = 0; kc < HH/FCK; kc++) {
#pragma unroll
        for (int p = 0; p < FCK/8; p++) {
            int kk = k0 + p*8;
            *(float4*)&As[kk*FCD + q4*4] =
                *(const float4*)(g_out2T + (kc*FCK + kk)*NN + rb + q4*4);
            *(float4*)&Bs[kk*FCD + q4*4] =
                *(const float4*)(WfcT + (long long)(kc*FCK + kk)*VV + cb + q4*4);
        }
        __syncthreads();

#pragma unroll 4
        for (int kk = 0; kk < FCK; kk++) {
            float4 a0 = *(const float4*)&As[kk*FCD + rBase];
            float4 a1 = *(const float4*)&As[kk*FCD + rBase + 4];
            ulonglong2 b0 = *(const ulonglong2*)&Bs[kk*FCD + cBase];
            ulonglong2 b1 = *(const ulonglong2*)&Bs[kk*FCD + cBase + 4];
            float av[8] = {a0.x, a0.y, a0.z, a0.w, a1.x, a1.y, a1.z, a1.w};
#pragma unroll
            for (int r = 0; r < 8; r++) {
                unsigned long long ar = pack2(av[r], av[r]);
                acc[r][0] = fma2(ar, b0.x, acc[r][0]);
                acc[r][1] = fma2(ar, b0.y, acc[r][1]);
                acc[r][2] = fma2(ar, b1.x, acc[r][2]);
                acc[r][3] = fma2(ar, b1.y, acc[r][3]);
            }
        }
        __syncthreads();
    }

    float4 bf0 = *(const float4*)(bfc + cb + cBase);
    float4 bf1 = *(const float4*)(bfc + cb + cBase + 4);
#pragma unroll
    for (int r = 0; r < 8; r++) {
        float2 p0 = unpack2(acc[r][0]);
        float2 p1 = unpack2(acc[r][1]);
        float2 p2 = unpack2(acc[r][2]);
        float2 p3 = unpack2(acc[r][3]);
        float4 o0 = make_float4(p0.x + bf0.x, p0.y + bf0.y,
                                p1.x + bf0.z, p1.y + bf0.w);
        float4 o1 = make_float4(p2.x + bf1.x, p2.y + bf1.y,
                                p3.x + bf1.z, p3.y + bf1.w);
        float* dst = logits + (long long)(rb + rBase + r)*VV + cb + cBase;
        *(float4*)(dst)     = o0;
        *(float4*)(dst + 4) = o1;
    }
}

// -------------------- launcher ----------------------------------------------
extern "C" void kernel_launch(void* const* d_in, const int* in_sizes, int n_in,
                              void* d_out, int out_size) {
    const void*  x      = d_in[0];
    const float* hidden = (const float*)d_in[1];
    const float* emb    = (const float*)d_in[2];
    const float* W_ih   = (const float*)d_in[3];
    const float* W_hh   = (const float*)d_in[4];
    const float* b_ih   = (const float*)d_in[5];
    const float* b_hh   = (const float*)d_in[6];
    const float* W1     = (const float*)d_in[7];
    const float* W2     = (const float*)d_in[8];
    const float* v      = (const float*)d_in[9];
    const float* Wp     = (const float*)d_in[10];
    const float* bp     = (const float*)d_in[11];
    const float* Wfc    = (const float*)d_in[12];
    const float* bfc    = (const float*)d_in[13];

    float* out     = (float*)d_out;
    float* logits  = out;
    float* hid_out = out + HID_OFF;
    float* w_out   = out + W_OFF;

    float *dW1T, *dW2T, *dWpT, *dWfcT;
    cudaGetSymbolAddress((void**)&dW1T,  g_W1T);
    cudaGetSymbolAddress((void**)&dW2T,  g_W2T);
    cudaGetSymbolAddress((void**)&dWpT,  g_WpT);
    cudaGetSymbolAddress((void**)&dWfcT, g_WfcT);

    cudaFuncSetAttribute(k_fc, cudaFuncAttributeMaxDynamicSharedMemorySize,
                         FC_SMEM);

    dim3 tb(32, 8);
    k_misc     <<<65, tb>>>((const int*)x, W1, W2, Wp);          // 1
    k_embed    <<<NN, HH>>>(x, emb, W_ih, b_ih, b_hh);           // 2
    k_transpose<<<dim3(4, 1000), tb>>>(Wfc, dWfcT, VV, HH);      // 3
    k_rnn      <<<BB, 256>>>(W_hh, hidden, hid_out);             // 4 <- ncu slot
    k_qk       <<<NN/QK_R, 256>>>(dW1T, dW2T);                   // 5
    k_attn     <<<dim3(TT, BB), 256>>>(v, w_out);                // 6
    k_proj     <<<NN/QK_R, 128>>>(dWpT, bp);                     // 7
    k_fc       <<<dim3(VV/FCD, NN/FCD), 256, FC_SMEM>>>(dWfcT, bfc, logits); // 8
}